// round 1
// baseline (speedup 1.0000x reference)
#include <cuda_runtime.h>
#include <cstdint>
#include <cstddef>

#define NB     32
#define NLAT   721
#define NLON   1440
#define NWORDS 45          // 1440 / 32
#define NTHREADS 256

// Cross-kernel scratch: per-row "has any valid sample" flag (no allocations allowed).
__device__ int g_row_valid[NB * NLAT];

// Bit-level NaN check (robust to fast-math folding of x != x).
__device__ __forceinline__ bool nan_f(float x) {
    return (__float_as_uint(x) & 0x7FFFFFFFu) > 0x7F800000u;
}

// Interpolated value at position i, given validity bitmask + row in smem.
// first/last are the first/last valid indices in the row (row guaranteed non-empty).
// At a valid position i this returns s[i] exactly (prev==next==i, t==0).
__device__ __forceinline__ float interp_at(
    int i, const unsigned* __restrict__ mask, const float* __restrict__ s,
    int firstv, int lastv)
{
    const int w = i >> 5;
    const int bpos = i & 31;

    // prev = largest valid j <= i, else lastv - NLON (circular wrap)
    unsigned lowbits = mask[w] & (0xFFFFFFFFu >> (31 - bpos));
    int prev;
    if (lowbits) {
        prev = (w << 5) + 31 - __clz(lowbits);
    } else {
        prev = lastv - NLON;
        #pragma unroll 1
        for (int ww = w - 1; ww >= 0; ww--) {
            unsigned mw = mask[ww];
            if (mw) { prev = (ww << 5) + 31 - __clz(mw); break; }
        }
    }

    // next = smallest valid j >= i, else firstv + NLON (circular wrap)
    unsigned hibits = mask[w] & (0xFFFFFFFFu << bpos);
    int nxt;
    if (hibits) {
        nxt = (w << 5) + __ffs(hibits) - 1;
    } else {
        nxt = firstv + NLON;
        #pragma unroll 1
        for (int ww = w + 1; ww < NWORDS; ww++) {
            unsigned mw = mask[ww];
            if (mw) { nxt = (ww << 5) + __ffs(mw) - 1; break; }
        }
    }

    const int dtot = nxt - prev;
    const float t = (dtot > 0) ? (float)(i - prev) / (float)dtot : 0.0f;
    const int pm = (prev < 0) ? prev + NLON : prev;
    const int nm = (nxt >= NLON) ? nxt - NLON : nxt;
    return s[pm] * (1.0f - t) + s[nm] * t;
}

// ---------------------------------------------------------------------------
// Kernel A: one CTA per (b, lat) row. Build validity bitmask, interpolate NaNs.
// ---------------------------------------------------------------------------
__global__ void __launch_bounds__(NTHREADS)
fill_rows_kernel(const float* __restrict__ sst, const int* __restrict__ lsm,
                 float* __restrict__ out)
{
    const int row = blockIdx.x;                    // b * NLAT + h
    const float* __restrict__ srow = sst + (size_t)row * NLON;
    const int*   __restrict__ mrow = lsm + (size_t)row * NLON;
    float*       __restrict__ orow = out + (size_t)row * NLON;

    __shared__ float    s[NLON];
    __shared__ unsigned mask[NWORDS];
    __shared__ int      s_first, s_last;

    const int tid = threadIdx.x;

    // Load row + build bitmask: lanes are 32 consecutive columns, so each
    // warp ballot is exactly one mask word. 6 strided passes cover 1440.
    #pragma unroll
    for (int k = 0; k < 6; k++) {
        const int i = k * NTHREADS + tid;
        const bool inb = (i < NLON);
        float v = 0.0f; int m = 1;
        if (inb) { v = srow[i]; m = mrow[i]; }
        const bool valid = inb && (m == 0) && !nan_f(v);
        const unsigned bal = __ballot_sync(0xFFFFFFFFu, valid);
        if (inb) s[i] = v;
        if ((tid & 31) == 0) {
            const int w = i >> 5;
            if (w < NWORDS) mask[w] = bal;
        }
    }
    __syncthreads();

    if (tid == 0) {
        int f = -1, la = -1;
        #pragma unroll 1
        for (int w = 0; w < NWORDS; w++) {
            unsigned mw = mask[w];
            if (mw) { f = (w << 5) + __ffs(mw) - 1; break; }
        }
        #pragma unroll 1
        for (int w = NWORDS - 1; w >= 0; w--) {
            unsigned mw = mask[w];
            if (mw) { la = (w << 5) + 31 - __clz(mw); break; }
        }
        s_first = f; s_last = la;
        g_row_valid[row] = (f >= 0) ? 1 : 0;
    }
    __syncthreads();

    const bool rv = (s_first >= 0);

    #pragma unroll
    for (int k = 0; k < 6; k++) {
        const int i = k * NTHREADS + tid;
        if (i >= NLON) break;
        const float sv = s[i];
        float o = sv;                        // keep finite sst; NaN if row empty
        if (nan_f(sv) && rv) {
            o = interp_at(i, mask, s, s_first, s_last);
        }
        orow[i] = o;
    }
}

// ---------------------------------------------------------------------------
// Kernel B: one CTA per batch. Find lastrow (max lat with any valid sample);
// for rows above it, fill NaN positions with the interpolated lastrow values.
// With random 50% masks this is a near no-op (lastrow == NLAT-1), but it is
// required for exact reference semantics.
// ---------------------------------------------------------------------------
__global__ void __launch_bounds__(NTHREADS)
fill_polar_kernel(const float* __restrict__ sst, const int* __restrict__ lsm,
                  float* __restrict__ out)
{
    const int b = blockIdx.x;
    const int tid = threadIdx.x;

    __shared__ int s_lastrow;
    if (tid == 0) s_lastrow = -1;
    __syncthreads();

    int loc = -1;
    for (int h = tid; h < NLAT; h += NTHREADS)
        if (g_row_valid[b * NLAT + h]) loc = (h > loc) ? h : loc;
    if (loc >= 0) atomicMax(&s_lastrow, loc);
    __syncthreads();

    const int lastrow = s_lastrow;
    if (lastrow < 0 || lastrow >= NLAT - 1) return;   // nothing above lastrow

    __shared__ float    s[NLON];
    __shared__ float    f[NLON];
    __shared__ unsigned mask[NWORDS];
    __shared__ int      s_first, s_last;

    const float* __restrict__ srow = sst + ((size_t)b * NLAT + lastrow) * NLON;
    const int*   __restrict__ mrow = lsm + ((size_t)b * NLAT + lastrow) * NLON;

    #pragma unroll
    for (int k = 0; k < 6; k++) {
        const int i = k * NTHREADS + tid;
        const bool inb = (i < NLON);
        float v = 0.0f; int m = 1;
        if (inb) { v = srow[i]; m = mrow[i]; }
        const bool valid = inb && (m == 0) && !nan_f(v);
        const unsigned bal = __ballot_sync(0xFFFFFFFFu, valid);
        if (inb) s[i] = v;
        if ((tid & 31) == 0) {
            const int w = i >> 5;
            if (w < NWORDS) mask[w] = bal;
        }
    }
    __syncthreads();

    if (tid == 0) {
        int ff = -1, la = -1;
        #pragma unroll 1
        for (int w = 0; w < NWORDS; w++) {
            unsigned mw = mask[w];
            if (mw) { ff = (w << 5) + __ffs(mw) - 1; break; }
        }
        #pragma unroll 1
        for (int w = NWORDS - 1; w >= 0; w--) {
            unsigned mw = mask[w];
            if (mw) { la = (w << 5) + 31 - __clz(mw); break; }
        }
        s_first = ff; s_last = la;
    }
    __syncthreads();

    // Full v of lastrow (reference uses v, not the masked output):
    // at valid positions this reduces to s[i] exactly.
    for (int i = tid; i < NLON; i += NTHREADS)
        f[i] = interp_at(i, mask, s, s_first, s_last);
    __syncthreads();

    for (int h = lastrow + 1; h < NLAT; h++) {
        const float* __restrict__ sr   = sst + ((size_t)b * NLAT + h) * NLON;
        float*       __restrict__ orow = out + ((size_t)b * NLAT + h) * NLON;
        for (int i = tid; i < NLON; i += NTHREADS) {
            if (nan_f(sr[i])) orow[i] = f[i];
        }
    }
}

// ---------------------------------------------------------------------------
extern "C" void kernel_launch(void* const* d_in, const int* in_sizes, int n_in,
                              void* d_out, int out_size)
{
    const float* sst = (const float*)d_in[0];
    const int*   lsm = (const int*)d_in[1];
    float*       out = (float*)d_out;

    fill_rows_kernel<<<NB * NLAT, NTHREADS>>>(sst, lsm, out);
    fill_polar_kernel<<<NB, NTHREADS>>>(sst, lsm, out);
}

// round 2
// speedup vs baseline: 1.1513x; 1.1513x over previous
#include <cuda_runtime.h>
#include <cstdint>
#include <cstddef>

#define NB     32
#define NLAT   721
#define NLON   1440
#define NVEC   360          // NLON / 4
#define NWORDS 45           // NLON / 32
#define NTH    128

// Cross-kernel scratch (no allocations allowed).
__device__ int g_row_valid[NB * NLAT];

__device__ __forceinline__ bool nan_f(float x) {
    return (__float_as_uint(x) & 0x7FFFFFFFu) > 0x7F800000u;
}

// Interpolated value at position i. Validity = !isnan. Row guaranteed non-empty.
// At a valid position returns s[i] exactly (prev==next==i, t==0).
__device__ __forceinline__ float interp_at(
    int i, const unsigned* __restrict__ mask, const float* __restrict__ s,
    int firstv, int lastv)
{
    const int w    = i >> 5;
    const int bpos = i & 31;

    unsigned lowbits = mask[w] & (0xFFFFFFFFu >> (31 - bpos));
    int prev;
    if (lowbits) {
        prev = (w << 5) + 31 - __clz(lowbits);
    } else {
        prev = lastv - NLON;                       // circular wrap
        #pragma unroll 1
        for (int ww = w - 1; ww >= 0; ww--) {
            unsigned mw = mask[ww];
            if (mw) { prev = (ww << 5) + 31 - __clz(mw); break; }
        }
    }

    unsigned hibits = mask[w] & (0xFFFFFFFFu << bpos);
    int nxt;
    if (hibits) {
        nxt = (w << 5) + __ffs(hibits) - 1;
    } else {
        nxt = firstv + NLON;                       // circular wrap
        #pragma unroll 1
        for (int ww = w + 1; ww < NWORDS; ww++) {
            unsigned mw = mask[ww];
            if (mw) { nxt = (ww << 5) + __ffs(mw) - 1; break; }
        }
    }

    const int dtot = nxt - prev;
    const float t  = (dtot > 0) ? __fdividef((float)(i - prev), (float)dtot) : 0.0f;
    const int pm = (prev < 0)      ? prev + NLON : prev;
    const int nm = (nxt  >= NLON)  ? nxt  - NLON : nxt;
    const float sp = s[pm];
    const float sn = s[nm];
    return fmaf(t, sn - sp, sp);
}

// ---------------------------------------------------------------------------
// Kernel A: one 128-thread CTA per (b, lat) row.
// All global loads front-batched as LDG.128, then mask build, then interp.
// ---------------------------------------------------------------------------
__global__ void __launch_bounds__(NTH)
fill_rows_kernel(const float4* __restrict__ sst4, float* __restrict__ out)
{
    const int row = blockIdx.x;                    // b * NLAT + h
    const float4* __restrict__ src = sst4 + (size_t)row * NVEC;
    float4*       __restrict__ dst = (float4*)(out + (size_t)row * NLON);

    __shared__ float4   s4[NVEC];
    __shared__ unsigned mask[NWORDS];
    __shared__ int      s_first, s_last;
    const float* s = (const float*)s4;

    const int t = threadIdx.x;

    // ---- Front-batched loads: 3 independent LDG.128 per thread ----
    float4 r0 = src[t];                            // vecs [0, 128)
    float4 r1 = src[t + 128];                      // vecs [128, 256)
    float4 r2;
    const bool has2 = (t < NVEC - 256);            // t < 104 -> vecs [256, 360)
    if (has2) r2 = src[t + 256];

    s4[t]       = r0;
    s4[t + 128] = r1;
    if (has2) s4[t + 256] = r2;
    __syncthreads();

    // ---- Build validity bitmask from SMEM (cheap, no DRAM latency) ----
    #pragma unroll
    for (int k = 0; k < 11; k++) {                 // 11 * 128 = 1408 elements
        const int i = k * NTH + t;
        const bool valid = !nan_f(s[i]);
        const unsigned bal = __ballot_sync(0xFFFFFFFFu, valid);
        if ((t & 31) == 0) mask[i >> 5] = bal;
    }
    if (t < 32) {                                  // tail: elements [1408, 1440)
        const int i = 1408 + t;
        const bool valid = !nan_f(s[i]);
        const unsigned bal = __ballot_sync(0xFFFFFFFFu, valid);
        if (t == 0) mask[44] = bal;
    }
    __syncthreads();

    if (t == 0) {
        int f = -1, la = -1;
        #pragma unroll 1
        for (int w = 0; w < NWORDS; w++) {
            unsigned mw = mask[w];
            if (mw) { f = (w << 5) + __ffs(mw) - 1; break; }
        }
        #pragma unroll 1
        for (int w = NWORDS - 1; w >= 0; w--) {
            unsigned mw = mask[w];
            if (mw) { la = (w << 5) + 31 - __clz(mw); break; }
        }
        s_first = f; s_last = la;
        g_row_valid[row] = (f >= 0) ? 1 : 0;
    }
    __syncthreads();

    const int firstv = s_first, lastv = s_last;
    const bool rv = (firstv >= 0);

    // ---- Interpolate + vectorized STG.128 output ----
    #pragma unroll
    for (int j = 0; j < 3; j++) {
        const int idx = t + j * NTH;
        if (j == 2 && !has2) break;
        float4 v = s4[idx];
        const int base = idx << 2;
        float o0 = v.x, o1 = v.y, o2 = v.z, o3 = v.w;
        if (rv) {
            if (nan_f(o0)) o0 = interp_at(base + 0, mask, s, firstv, lastv);
            if (nan_f(o1)) o1 = interp_at(base + 1, mask, s, firstv, lastv);
            if (nan_f(o2)) o2 = interp_at(base + 2, mask, s, firstv, lastv);
            if (nan_f(o3)) o3 = interp_at(base + 3, mask, s, firstv, lastv);
        }
        dst[idx] = make_float4(o0, o1, o2, o3);
    }
}

// ---------------------------------------------------------------------------
// Kernel B: one CTA per batch — polar fill above lastrow (near no-op for
// random masks, required for exact reference semantics).
// ---------------------------------------------------------------------------
__global__ void __launch_bounds__(256)
fill_polar_kernel(const float* __restrict__ sst, float* __restrict__ out)
{
    const int b = blockIdx.x;
    const int tid = threadIdx.x;

    __shared__ int s_lastrow;
    if (tid == 0) s_lastrow = -1;
    __syncthreads();

    int loc = -1;
    for (int h = tid; h < NLAT; h += 256)
        if (g_row_valid[b * NLAT + h]) loc = (h > loc) ? h : loc;
    if (loc >= 0) atomicMax(&s_lastrow, loc);
    __syncthreads();

    const int lastrow = s_lastrow;
    if (lastrow < 0 || lastrow >= NLAT - 1) return;

    __shared__ float    s[NLON];
    __shared__ float    f[NLON];
    __shared__ unsigned mask[NWORDS];
    __shared__ int      s_first, s_last;

    const float* __restrict__ srow = sst + ((size_t)b * NLAT + lastrow) * NLON;

    for (int i = tid; i < NLON; i += 256) s[i] = srow[i];
    __syncthreads();

    #pragma unroll
    for (int k = 0; k < 6; k++) {
        const int i = k * 256 + tid;
        const bool inb = (i < NLON);
        const bool valid = inb && !nan_f(inb ? s[i] : 0.0f);
        const unsigned bal = __ballot_sync(0xFFFFFFFFu, valid);
        if ((tid & 31) == 0) {
            const int w = i >> 5;
            if (w < NWORDS) mask[w] = bal;
        }
    }
    __syncthreads();

    if (tid == 0) {
        int ff = -1, la = -1;
        #pragma unroll 1
        for (int w = 0; w < NWORDS; w++) {
            unsigned mw = mask[w];
            if (mw) { ff = (w << 5) + __ffs(mw) - 1; break; }
        }
        #pragma unroll 1
        for (int w = NWORDS - 1; w >= 0; w--) {
            unsigned mw = mask[w];
            if (mw) { la = (w << 5) + 31 - __clz(mw); break; }
        }
        s_first = ff; s_last = la;
    }
    __syncthreads();

    for (int i = tid; i < NLON; i += 256)
        f[i] = interp_at(i, mask, s, s_first, s_last);
    __syncthreads();

    for (int h = lastrow + 1; h < NLAT; h++) {
        const float* __restrict__ sr   = sst + ((size_t)b * NLAT + h) * NLON;
        float*       __restrict__ orow = out + ((size_t)b * NLAT + h) * NLON;
        for (int i = tid; i < NLON; i += 256) {
            if (nan_f(sr[i])) orow[i] = f[i];
        }
    }
}

// ---------------------------------------------------------------------------
extern "C" void kernel_launch(void* const* d_in, const int* in_sizes, int n_in,
                              void* d_out, int out_size)
{
    const float* sst = (const float*)d_in[0];
    float*       out = (float*)d_out;

    fill_rows_kernel<<<NB * NLAT, NTH>>>((const float4*)sst, out);
    fill_polar_kernel<<<NB, 256>>>(sst, out);
}